// round 4
// baseline (speedup 1.0000x reference)
#include <cuda_runtime.h>
#include <cstdint>

#define N_NODES_MAX 50000
#define N_EDGES_MAX 800000
#define F 128

// ---------- scratch (device globals; no allocation allowed) ----------
__device__ int   g_deg_out[N_NODES_MAX];
__device__ int   g_deg_in[N_NODES_MAX];
__device__ int   g_cursor[N_NODES_MAX];        // running write position per dst row
__device__ int   g_row_ptr[N_NODES_MAX + 1];
__device__ int   g_col_idx[N_EDGES_MAX];
__device__ float g_y[(size_t)N_NODES_MAX * F];

// ---------- 1. zero degree arrays ----------
__global__ void zero_kernel(int n) {
    int i = blockIdx.x * blockDim.x + threadIdx.x;
    if (i < n) {
        g_deg_out[i] = 0;
        g_deg_in[i]  = 0;
    }
}

// ---------- 2. degree histogram ----------
__global__ void degree_kernel(const int* __restrict__ src,
                              const int* __restrict__ dst, int e) {
    int i = blockIdx.x * blockDim.x + threadIdx.x;
    if (i < e) {
        atomicAdd(&g_deg_out[src[i]], 1);
        atomicAdd(&g_deg_in[dst[i]], 1);
    }
}

// ---------- 3. exclusive scan of deg_in -> row_ptr + cursor (single block) ----------
__global__ void scan_kernel(int n) {
    __shared__ int s[1024];
    int tid = threadIdx.x;
    int chunk = (n + 1023) >> 10;
    int start = min(tid * chunk, n);
    int end   = min(start + chunk, n);
    int sum = 0;
    for (int i = start; i < end; i++) sum += g_deg_in[i];
    s[tid] = sum;
    __syncthreads();
    for (int off = 1; off < 1024; off <<= 1) {
        int v = (tid >= off) ? s[tid - off] : 0;
        __syncthreads();
        s[tid] += v;
        __syncthreads();
    }
    int off = (tid == 0) ? 0 : s[tid - 1];
    for (int i = start; i < end; i++) {
        g_row_ptr[i] = off;
        g_cursor[i]  = off;       // cursor starts at row start; fill atomics on it
        off += g_deg_in[i];
    }
    if (tid == 1023) g_row_ptr[n] = s[1023];
}

// ---------- 4. scatter edges into CSR (sorted by dst) ----------
__global__ void fill_kernel(const int* __restrict__ src,
                            const int* __restrict__ dst, int e) {
    int i = blockIdx.x * blockDim.x + threadIdx.x;
    if (i < e) {
        int p = atomicAdd(&g_cursor[dst[i]], 1);
        g_col_idx[p] = src[i];
    }
}

// ---------- 5. y = (x * rsqrt(max(deg_out,1))) @ W via tf32 tensor cores ----------
// Block: 128x128 output, 256 threads = 8 warps arranged 4(M) x 2(N).
// Warp tile 32x64 = 2(M) x 8(N) m16n8k8 mma tiles, K loop 128/8 = 16 steps.
#define BM 128
#define APAD 132      // A smem row stride (conflict-free frag loads)
#define BPAD 136      // B smem row stride (conflict-free frag loads)
#define GEMM_SMEM_BYTES ((BM * APAD + 128 * BPAD) * 4)

__device__ __forceinline__ unsigned f2tf32(float f) {
    unsigned r;
    asm("cvt.rna.tf32.f32 %0, %1;" : "=r"(r) : "f"(f));
    return r;
}

__global__ void gemm_kernel(const float* __restrict__ x,
                            const float* __restrict__ W, int n) {
    extern __shared__ float smem[];
    float* As = smem;               // [BM][APAD]
    float* Bs = smem + BM * APAD;   // [128][BPAD]

    int tid  = threadIdx.x;          // 0..255
    int base = blockIdx.x * BM;
    int r0 = tid >> 5;               // 0..7
    int c0 = (tid & 31) << 2;        // 0..124

    // stage A (scaled + tf32-rounded) and B (tf32-rounded) into smem
#pragma unroll
    for (int p = 0; p < 16; p++) {
        int r = r0 + (p << 3);
        float4 w = *(const float4*)&W[r * 128 + c0];
        w.x = __uint_as_float(f2tf32(w.x));
        w.y = __uint_as_float(f2tf32(w.y));
        w.z = __uint_as_float(f2tf32(w.z));
        w.w = __uint_as_float(f2tf32(w.w));
        *(float4*)&Bs[r * BPAD + c0] = w;

        int gr = base + r;
        float4 v = make_float4(0.f, 0.f, 0.f, 0.f);
        if (gr < n) {
            v = *(const float4*)&x[(size_t)gr * F + c0];
            float sc = rsqrtf(fmaxf((float)g_deg_out[gr], 1.0f));
            v.x = __uint_as_float(f2tf32(v.x * sc));
            v.y = __uint_as_float(f2tf32(v.y * sc));
            v.z = __uint_as_float(f2tf32(v.z * sc));
            v.w = __uint_as_float(f2tf32(v.w * sc));
        }
        *(float4*)&As[r * APAD + c0] = v;
    }
    __syncthreads();

    int warp = tid >> 5;
    int lane = tid & 31;
    int wm = warp & 3;       // warp M index 0..3
    int wn = warp >> 2;      // warp N index 0..1
    int g  = lane >> 2;      // group 0..7
    int t  = lane & 3;       // thread-in-group 0..3

    float c[2][8][4];
#pragma unroll
    for (int mt = 0; mt < 2; mt++)
#pragma unroll
        for (int nt = 0; nt < 8; nt++)
#pragma unroll
            for (int q = 0; q < 4; q++) c[mt][nt][q] = 0.f;

    const float* Abase = As + (wm * 32 + g) * APAD + t;
    const float* Bbase = Bs + t * BPAD + wn * 64 + g;

#pragma unroll
    for (int k = 0; k < 128; k += 8) {
        unsigned a[2][4];
#pragma unroll
        for (int mt = 0; mt < 2; mt++) {
            const float* Ap = Abase + mt * 16 * APAD + k;
            a[mt][0] = __float_as_uint(Ap[0]);
            a[mt][1] = __float_as_uint(Ap[8 * APAD]);
            a[mt][2] = __float_as_uint(Ap[4]);
            a[mt][3] = __float_as_uint(Ap[8 * APAD + 4]);
        }
        unsigned b[8][2];
#pragma unroll
        for (int nt = 0; nt < 8; nt++) {
            const float* Bp = Bbase + k * BPAD + nt * 8;
            b[nt][0] = __float_as_uint(Bp[0]);
            b[nt][1] = __float_as_uint(Bp[4 * BPAD]);
        }
#pragma unroll
        for (int mt = 0; mt < 2; mt++)
#pragma unroll
            for (int nt = 0; nt < 8; nt++) {
                asm volatile(
                    "mma.sync.aligned.m16n8k8.row.col.f32.tf32.tf32.f32 "
                    "{%0,%1,%2,%3}, {%4,%5,%6,%7}, {%8,%9}, {%0,%1,%2,%3};\n"
                    : "+f"(c[mt][nt][0]), "+f"(c[mt][nt][1]),
                      "+f"(c[mt][nt][2]), "+f"(c[mt][nt][3])
                    : "r"(a[mt][0]), "r"(a[mt][1]), "r"(a[mt][2]), "r"(a[mt][3]),
                      "r"(b[nt][0]), "r"(b[nt][1]));
            }
    }

    // epilogue: c0/c1 = row g cols (2t, 2t+1); c2/c3 = row g+8
#pragma unroll
    for (int mt = 0; mt < 2; mt++) {
#pragma unroll
        for (int half = 0; half < 2; half++) {
            int row = base + wm * 32 + mt * 16 + half * 8 + g;
            if (row < n) {
                float* yp = g_y + (size_t)row * F + wn * 64 + 2 * t;
#pragma unroll
                for (int nt = 0; nt < 8; nt++) {
                    float2 v = make_float2(c[mt][nt][half * 2],
                                           c[mt][nt][half * 2 + 1]);
                    *(float2*)(yp + nt * 8) = v;
                }
            }
        }
    }
}

// ---------- 6. aggregation + right-norm + bias (one warp per node) ----------
__global__ void agg_kernel(const float* __restrict__ bias,
                           float* __restrict__ out, int n) {
    int node = (blockIdx.x * blockDim.x + threadIdx.x) >> 5;
    int lane = threadIdx.x & 31;
    if (node >= n) return;

    int beg = g_row_ptr[node];
    int end = g_row_ptr[node + 1];

    float4 acc = make_float4(0.f, 0.f, 0.f, 0.f);
    int j = beg;
    while (j + 32 <= end) {
        int idx = g_col_idx[j + lane];
#pragma unroll
        for (int i = 0; i < 32; i++) {
            int s = __shfl_sync(0xffffffffu, idx, i);
            float4 v = *(const float4*)(g_y + ((size_t)s << 7) + (lane << 2));
            acc.x += v.x; acc.y += v.y; acc.z += v.z; acc.w += v.w;
        }
        j += 32;
    }
    int rem = end - j;
    if (rem > 0) {
        int idx = (lane < rem) ? g_col_idx[j + lane] : 0;
        for (int i = 0; i < rem; i++) {
            int s = __shfl_sync(0xffffffffu, idx, i);
            float4 v = *(const float4*)(g_y + ((size_t)s << 7) + (lane << 2));
            acc.x += v.x; acc.y += v.y; acc.z += v.z; acc.w += v.w;
        }
    }

    float sc = rsqrtf(fmaxf((float)(end - beg), 1.0f));
    float4 b = ((const float4*)bias)[lane];
    float4 o = make_float4(acc.x * sc + b.x, acc.y * sc + b.y,
                           acc.z * sc + b.z, acc.w * sc + b.w);
    *(float4*)(out + ((size_t)node << 7) + (lane << 2)) = o;
}

// ---------- launch ----------
extern "C" void kernel_launch(void* const* d_in, const int* in_sizes, int n_in,
                              void* d_out, int out_size) {
    const float* x    = (const float*)d_in[0];
    const int*   src  = (const int*)d_in[1];
    const int*   dst  = (const int*)d_in[2];
    const float* W    = (const float*)d_in[3];
    const float* bias = (const float*)d_in[4];
    float* out = (float*)d_out;

    int n = in_sizes[0] / F;
    int e = in_sizes[1];

    cudaFuncSetAttribute(gemm_kernel,
                         cudaFuncAttributeMaxDynamicSharedMemorySize,
                         GEMM_SMEM_BYTES);

    zero_kernel<<<(n + 255) / 256, 256>>>(n);
    degree_kernel<<<(e + 255) / 256, 256>>>(src, dst, e);
    scan_kernel<<<1, 1024>>>(n);
    fill_kernel<<<(e + 255) / 256, 256>>>(src, dst, e);
    gemm_kernel<<<(n + BM - 1) / BM, 256, GEMM_SMEM_BYTES>>>(x, W, n);
    agg_kernel<<<(n * 32 + 255) / 256, 256>>>(bias, out, n);
}

// round 8
// speedup vs baseline: 1.0714x; 1.0714x over previous
#include <cuda_runtime.h>
#include <cuda_fp16.h>
#include <cstdint>

#define N_NODES_MAX 50000
#define N_EDGES_MAX 800000
#define F 128

// ---------- scratch (device globals; no allocation allowed) ----------
__device__ int    g_deg_out[N_NODES_MAX];
__device__ int    g_deg_in[N_NODES_MAX];
__device__ int    g_cursor[N_NODES_MAX];
__device__ int    g_row_ptr[N_NODES_MAX + 1];
__device__ int    g_col_idx[N_EDGES_MAX];
__device__ __half g_yh[(size_t)N_NODES_MAX * F];   // y in fp16 (halves agg traffic)

// ---------- 1. zero degree arrays ----------
__global__ void zero_kernel(int n) {
    int i = blockIdx.x * blockDim.x + threadIdx.x;
    if (i < n) {
        g_deg_out[i] = 0;
        g_deg_in[i]  = 0;
    }
}

// ---------- 2. degree histogram, 4 edges/thread (MLP=8 atomics in flight) ----------
__global__ void degree_kernel(const int* __restrict__ src,
                              const int* __restrict__ dst, int e) {
    int i = (blockIdx.x * blockDim.x + threadIdx.x) * 4;
    if (i + 4 <= e) {
        int4 s = *(const int4*)(src + i);
        int4 d = *(const int4*)(dst + i);
        atomicAdd(&g_deg_out[s.x], 1);
        atomicAdd(&g_deg_out[s.y], 1);
        atomicAdd(&g_deg_out[s.z], 1);
        atomicAdd(&g_deg_out[s.w], 1);
        atomicAdd(&g_deg_in[d.x], 1);
        atomicAdd(&g_deg_in[d.y], 1);
        atomicAdd(&g_deg_in[d.z], 1);
        atomicAdd(&g_deg_in[d.w], 1);
    } else {
        for (int j = i; j < e; j++) {
            atomicAdd(&g_deg_out[src[j]], 1);
            atomicAdd(&g_deg_in[dst[j]], 1);
        }
    }
}

// ---------- 3. exclusive scan of deg_in -> row_ptr + cursor (single block) ----------
__global__ void scan_kernel(int n) {
    __shared__ int s[1024];
    int tid = threadIdx.x;
    int chunk = (n + 1023) >> 10;
    int start = min(tid * chunk, n);
    int end   = min(start + chunk, n);
    int sum = 0;
    for (int i = start; i < end; i++) sum += g_deg_in[i];
    s[tid] = sum;
    __syncthreads();
    for (int off = 1; off < 1024; off <<= 1) {
        int v = (tid >= off) ? s[tid - off] : 0;
        __syncthreads();
        s[tid] += v;
        __syncthreads();
    }
    int off = (tid == 0) ? 0 : s[tid - 1];
    for (int i = start; i < end; i++) {
        g_row_ptr[i] = off;
        g_cursor[i]  = off;
        off += g_deg_in[i];
    }
    if (tid == 1023) g_row_ptr[n] = s[1023];
}

// ---------- 4. scatter edges into CSR, 4 edges/thread ----------
__global__ void fill_kernel(const int* __restrict__ src,
                            const int* __restrict__ dst, int e) {
    int i = (blockIdx.x * blockDim.x + threadIdx.x) * 4;
    if (i + 4 <= e) {
        int4 s = *(const int4*)(src + i);
        int4 d = *(const int4*)(dst + i);
        int p0 = atomicAdd(&g_cursor[d.x], 1);
        int p1 = atomicAdd(&g_cursor[d.y], 1);
        int p2 = atomicAdd(&g_cursor[d.z], 1);
        int p3 = atomicAdd(&g_cursor[d.w], 1);
        g_col_idx[p0] = s.x;
        g_col_idx[p1] = s.y;
        g_col_idx[p2] = s.z;
        g_col_idx[p3] = s.w;
    } else {
        for (int j = i; j < e; j++) {
            int p = atomicAdd(&g_cursor[dst[j]], 1);
            g_col_idx[p] = src[j];
        }
    }
}

// ---------- 5. y = (x * rsqrt(max(deg_out,1))) @ W via tf32 tensor cores ----------
#define BM 128
#define APAD 132
#define BPAD 136
#define GEMM_SMEM_BYTES ((BM * APAD + 128 * BPAD) * 4)

__device__ __forceinline__ unsigned f2tf32(float f) {
    unsigned r;
    asm("cvt.rna.tf32.f32 %0, %1;" : "=r"(r) : "f"(f));
    return r;
}

__global__ void gemm_kernel(const float* __restrict__ x,
                            const float* __restrict__ W, int n) {
    extern __shared__ float smem[];
    float* As = smem;               // [BM][APAD]
    float* Bs = smem + BM * APAD;   // [128][BPAD]

    int tid  = threadIdx.x;
    int base = blockIdx.x * BM;
    int r0 = tid >> 5;
    int c0 = (tid & 31) << 2;

#pragma unroll
    for (int p = 0; p < 16; p++) {
        int r = r0 + (p << 3);
        float4 w = *(const float4*)&W[r * 128 + c0];
        w.x = __uint_as_float(f2tf32(w.x));
        w.y = __uint_as_float(f2tf32(w.y));
        w.z = __uint_as_float(f2tf32(w.z));
        w.w = __uint_as_float(f2tf32(w.w));
        *(float4*)&Bs[r * BPAD + c0] = w;

        int gr = base + r;
        float4 v = make_float4(0.f, 0.f, 0.f, 0.f);
        if (gr < n) {
            v = *(const float4*)&x[(size_t)gr * F + c0];
            float sc = rsqrtf(fmaxf((float)g_deg_out[gr], 1.0f));
            v.x = __uint_as_float(f2tf32(v.x * sc));
            v.y = __uint_as_float(f2tf32(v.y * sc));
            v.z = __uint_as_float(f2tf32(v.z * sc));
            v.w = __uint_as_float(f2tf32(v.w * sc));
        }
        *(float4*)&As[r * APAD + c0] = v;
    }
    __syncthreads();

    int warp = tid >> 5;
    int lane = tid & 31;
    int wm = warp & 3;
    int wn = warp >> 2;
    int g  = lane >> 2;
    int t  = lane & 3;

    float c[2][8][4];
#pragma unroll
    for (int mt = 0; mt < 2; mt++)
#pragma unroll
        for (int nt = 0; nt < 8; nt++)
#pragma unroll
            for (int q = 0; q < 4; q++) c[mt][nt][q] = 0.f;

    const float* Abase = As + (wm * 32 + g) * APAD + t;
    const float* Bbase = Bs + t * BPAD + wn * 64 + g;

#pragma unroll
    for (int k = 0; k < 128; k += 8) {
        unsigned a[2][4];
#pragma unroll
        for (int mt = 0; mt < 2; mt++) {
            const float* Ap = Abase + mt * 16 * APAD + k;
            a[mt][0] = __float_as_uint(Ap[0]);
            a[mt][1] = __float_as_uint(Ap[8 * APAD]);
            a[mt][2] = __float_as_uint(Ap[4]);
            a[mt][3] = __float_as_uint(Ap[8 * APAD + 4]);
        }
        unsigned b[8][2];
#pragma unroll
        for (int nt = 0; nt < 8; nt++) {
            const float* Bp = Bbase + k * BPAD + nt * 8;
            b[nt][0] = __float_as_uint(Bp[0]);
            b[nt][1] = __float_as_uint(Bp[4 * BPAD]);
        }
#pragma unroll
        for (int mt = 0; mt < 2; mt++)
#pragma unroll
            for (int nt = 0; nt < 8; nt++) {
                asm volatile(
                    "mma.sync.aligned.m16n8k8.row.col.f32.tf32.tf32.f32 "
                    "{%0,%1,%2,%3}, {%4,%5,%6,%7}, {%8,%9}, {%0,%1,%2,%3};\n"
                    : "+f"(c[mt][nt][0]), "+f"(c[mt][nt][1]),
                      "+f"(c[mt][nt][2]), "+f"(c[mt][nt][3])
                    : "r"(a[mt][0]), "r"(a[mt][1]), "r"(a[mt][2]), "r"(a[mt][3]),
                      "r"(b[nt][0]), "r"(b[nt][1]));
            }
    }

    // epilogue -> fp16 y. c0/c1 = row g cols (2t,2t+1); c2/c3 = row g+8.
#pragma unroll
    for (int mt = 0; mt < 2; mt++) {
#pragma unroll
        for (int half_i = 0; half_i < 2; half_i++) {
            int row = base + wm * 32 + mt * 16 + half_i * 8 + g;
            if (row < n) {
                __half* yp = g_yh + (size_t)row * F + wn * 64 + 2 * t;
#pragma unroll
                for (int nt = 0; nt < 8; nt++) {
                    __half2 h = __floats2half2_rn(c[mt][nt][half_i * 2],
                                                  c[mt][nt][half_i * 2 + 1]);
                    *(__half2*)(yp + nt * 8) = h;
                }
            }
        }
    }
}

// ---------- 6. aggregation (fp16 y, fp32 accum) + right-norm + bias ----------
__global__ void agg_kernel(const float* __restrict__ bias,
                           float* __restrict__ out, int n) {
    int node = (blockIdx.x * blockDim.x + threadIdx.x) >> 5;
    int lane = threadIdx.x & 31;
    if (node >= n) return;

    int beg = g_row_ptr[node];
    int end = g_row_ptr[node + 1];

    const __half* yh = g_yh;
    float4 acc = make_float4(0.f, 0.f, 0.f, 0.f);
    int j = beg;
    while (j + 32 <= end) {
        int idx = g_col_idx[j + lane];
#pragma unroll
        for (int i = 0; i < 32; i++) {
            int s = __shfl_sync(0xffffffffu, idx, i);
            uint2 raw = *(const uint2*)(yh + ((size_t)s << 7) + (lane << 2));
            float2 f0 = __half22float2(*(__half2*)&raw.x);
            float2 f1 = __half22float2(*(__half2*)&raw.y);
            acc.x += f0.x; acc.y += f0.y; acc.z += f1.x; acc.w += f1.y;
        }
        j += 32;
    }
    int rem = end - j;
    if (rem > 0) {
        int idx = (lane < rem) ? g_col_idx[j + lane] : 0;
        for (int i = 0; i < rem; i++) {
            int s = __shfl_sync(0xffffffffu, idx, i);
            uint2 raw = *(const uint2*)(yh + ((size_t)s << 7) + (lane << 2));
            float2 f0 = __half22float2(*(__half2*)&raw.x);
            float2 f1 = __half22float2(*(__half2*)&raw.y);
            acc.x += f0.x; acc.y += f0.y; acc.z += f1.x; acc.w += f1.y;
        }
    }

    float sc = rsqrtf(fmaxf((float)(end - beg), 1.0f));
    float4 b = ((const float4*)bias)[lane];
    float4 o = make_float4(acc.x * sc + b.x, acc.y * sc + b.y,
                           acc.z * sc + b.z, acc.w * sc + b.w);
    *(float4*)(out + ((size_t)node << 7) + (lane << 2)) = o;
}

// ---------- launch ----------
extern "C" void kernel_launch(void* const* d_in, const int* in_sizes, int n_in,
                              void* d_out, int out_size) {
    const float* x    = (const float*)d_in[0];
    const int*   src  = (const int*)d_in[1];
    const int*   dst  = (const int*)d_in[2];
    const float* W    = (const float*)d_in[3];
    const float* bias = (const float*)d_in[4];
    float* out = (float*)d_out;

    int n = in_sizes[0] / F;
    int e = in_sizes[1];
    int e4 = (e + 3) / 4;   // threads for 4-edge-batched kernels

    cudaFuncSetAttribute(gemm_kernel,
                         cudaFuncAttributeMaxDynamicSharedMemorySize,
                         GEMM_SMEM_BYTES);

    zero_kernel<<<(n + 255) / 256, 256>>>(n);
    degree_kernel<<<(e4 + 255) / 256, 256>>>(src, dst, e);
    scan_kernel<<<1, 1024>>>(n);
    fill_kernel<<<(e4 + 255) / 256, 256>>>(src, dst, e);
    gemm_kernel<<<(n + BM - 1) / BM, 256, GEMM_SMEM_BYTES>>>(x, W, n);
    agg_kernel<<<(n * 32 + 255) / 256, 256>>>(bias, out, n);
}

// round 12
// speedup vs baseline: 1.1248x; 1.0498x over previous
#include <cuda_runtime.h>
#include <cuda_fp16.h>
#include <cstdint>

#define N_NODES_MAX 50000
#define N_EDGES_MAX 800000
#define F 128

// ---------- scratch (device globals; no allocation allowed) ----------
__device__ int    g_deg_out[N_NODES_MAX];
__device__ int    g_deg_in[N_NODES_MAX];
__device__ int    g_cursor[N_NODES_MAX];
__device__ int    g_row_ptr[N_NODES_MAX + 1];
__device__ int    g_col_idx[N_EDGES_MAX];
__device__ __half g_yh[(size_t)N_NODES_MAX * F];   // y in fp16

// ---------- 1. zero degree arrays ----------
__global__ void zero_kernel(int n) {
    int i = blockIdx.x * blockDim.x + threadIdx.x;
    if (i < n) {
        g_deg_out[i] = 0;
        g_deg_in[i]  = 0;
    }
}

// ---------- 2. degree histogram, 4 edges/thread ----------
__global__ void degree_kernel(const int* __restrict__ src,
                              const int* __restrict__ dst, int e) {
    int i = (blockIdx.x * blockDim.x + threadIdx.x) * 4;
    if (i + 4 <= e) {
        int4 s = *(const int4*)(src + i);
        int4 d = *(const int4*)(dst + i);
        atomicAdd(&g_deg_out[s.x], 1);
        atomicAdd(&g_deg_out[s.y], 1);
        atomicAdd(&g_deg_out[s.z], 1);
        atomicAdd(&g_deg_out[s.w], 1);
        atomicAdd(&g_deg_in[d.x], 1);
        atomicAdd(&g_deg_in[d.y], 1);
        atomicAdd(&g_deg_in[d.z], 1);
        atomicAdd(&g_deg_in[d.w], 1);
    } else {
        for (int j = i; j < e; j++) {
            atomicAdd(&g_deg_out[src[j]], 1);
            atomicAdd(&g_deg_in[dst[j]], 1);
        }
    }
}

// ---------- 3. exclusive scan of deg_in -> row_ptr + cursor (single block) ----------
__global__ void scan_kernel(int n) {
    __shared__ int s[1024];
    int tid = threadIdx.x;
    int chunk = (n + 1023) >> 10;
    int start = min(tid * chunk, n);
    int end   = min(start + chunk, n);
    int sum = 0;
    for (int i = start; i < end; i++) sum += g_deg_in[i];
    s[tid] = sum;
    __syncthreads();
    for (int off = 1; off < 1024; off <<= 1) {
        int v = (tid >= off) ? s[tid - off] : 0;
        __syncthreads();
        s[tid] += v;
        __syncthreads();
    }
    int off = (tid == 0) ? 0 : s[tid - 1];
    for (int i = start; i < end; i++) {
        g_row_ptr[i] = off;
        g_cursor[i]  = off;
        off += g_deg_in[i];
    }
    if (tid == 1023) g_row_ptr[n] = s[1023];
}

// ---------- 4+5 fused: gemm tiles (blocks < gemm_blocks) + CSR fill (rest) ----------
#define BM 128
#define APAD 132
#define BPAD 136
#define GEMM_SMEM_BYTES ((BM * APAD + 128 * BPAD) * 4)
#define FILL_EPT 8   // edges per thread in fill path

__device__ __forceinline__ unsigned f2tf32(float f) {
    unsigned r;
    asm("cvt.rna.tf32.f32 %0, %1;" : "=r"(r) : "f"(f));
    return r;
}

__device__ __forceinline__ void gemm_body(const float* __restrict__ x,
                                          const float* __restrict__ W,
                                          int n, int blk) {
    extern __shared__ float smem[];
    float* As = smem;               // [BM][APAD]
    float* Bs = smem + BM * APAD;   // [128][BPAD]

    int tid  = threadIdx.x;
    int base = blk * BM;
    int r0 = tid >> 5;
    int c0 = (tid & 31) << 2;

#pragma unroll
    for (int p = 0; p < 16; p++) {
        int r = r0 + (p << 3);
        float4 w = *(const float4*)&W[r * 128 + c0];
        w.x = __uint_as_float(f2tf32(w.x));
        w.y = __uint_as_float(f2tf32(w.y));
        w.z = __uint_as_float(f2tf32(w.z));
        w.w = __uint_as_float(f2tf32(w.w));
        *(float4*)&Bs[r * BPAD + c0] = w;

        int gr = base + r;
        float4 v = make_float4(0.f, 0.f, 0.f, 0.f);
        if (gr < n) {
            v = *(const float4*)&x[(size_t)gr * F + c0];
            float sc = rsqrtf(fmaxf((float)g_deg_out[gr], 1.0f));
            v.x = __uint_as_float(f2tf32(v.x * sc));
            v.y = __uint_as_float(f2tf32(v.y * sc));
            v.z = __uint_as_float(f2tf32(v.z * sc));
            v.w = __uint_as_float(f2tf32(v.w * sc));
        }
        *(float4*)&As[r * APAD + c0] = v;
    }
    __syncthreads();

    int warp = tid >> 5;
    int lane = tid & 31;
    int wm = warp & 3;
    int wn = warp >> 2;
    int g  = lane >> 2;
    int t  = lane & 3;

    float c[2][8][4];
#pragma unroll
    for (int mt = 0; mt < 2; mt++)
#pragma unroll
        for (int nt = 0; nt < 8; nt++)
#pragma unroll
            for (int q = 0; q < 4; q++) c[mt][nt][q] = 0.f;

    const float* Abase = As + (wm * 32 + g) * APAD + t;
    const float* Bbase = Bs + t * BPAD + wn * 64 + g;

#pragma unroll
    for (int k = 0; k < 128; k += 8) {
        unsigned a[2][4];
#pragma unroll
        for (int mt = 0; mt < 2; mt++) {
            const float* Ap = Abase + mt * 16 * APAD + k;
            a[mt][0] = __float_as_uint(Ap[0]);
            a[mt][1] = __float_as_uint(Ap[8 * APAD]);
            a[mt][2] = __float_as_uint(Ap[4]);
            a[mt][3] = __float_as_uint(Ap[8 * APAD + 4]);
        }
        unsigned b[8][2];
#pragma unroll
        for (int nt = 0; nt < 8; nt++) {
            const float* Bp = Bbase + k * BPAD + nt * 8;
            b[nt][0] = __float_as_uint(Bp[0]);
            b[nt][1] = __float_as_uint(Bp[4 * BPAD]);
        }
#pragma unroll
        for (int mt = 0; mt < 2; mt++)
#pragma unroll
            for (int nt = 0; nt < 8; nt++) {
                asm volatile(
                    "mma.sync.aligned.m16n8k8.row.col.f32.tf32.tf32.f32 "
                    "{%0,%1,%2,%3}, {%4,%5,%6,%7}, {%8,%9}, {%0,%1,%2,%3};\n"
                    : "+f"(c[mt][nt][0]), "+f"(c[mt][nt][1]),
                      "+f"(c[mt][nt][2]), "+f"(c[mt][nt][3])
                    : "r"(a[mt][0]), "r"(a[mt][1]), "r"(a[mt][2]), "r"(a[mt][3]),
                      "r"(b[nt][0]), "r"(b[nt][1]));
            }
    }

#pragma unroll
    for (int mt = 0; mt < 2; mt++) {
#pragma unroll
        for (int half_i = 0; half_i < 2; half_i++) {
            int row = base + wm * 32 + mt * 16 + half_i * 8 + g;
            if (row < n) {
                __half* yp = g_yh + (size_t)row * F + wn * 64 + 2 * t;
#pragma unroll
                for (int nt = 0; nt < 8; nt++) {
                    __half2 h = __floats2half2_rn(c[mt][nt][half_i * 2],
                                                  c[mt][nt][half_i * 2 + 1]);
                    *(__half2*)(yp + nt * 8) = h;
                }
            }
        }
    }
}

__device__ __forceinline__ void fill_body(const int* __restrict__ src,
                                          const int* __restrict__ dst,
                                          int e, int blk) {
    int i = (blk * blockDim.x + threadIdx.x) * FILL_EPT;
    if (i + FILL_EPT <= e) {
#pragma unroll
        for (int h = 0; h < FILL_EPT / 4; h++) {
            int4 s = *(const int4*)(src + i + h * 4);
            int4 d = *(const int4*)(dst + i + h * 4);
            int p0 = atomicAdd(&g_cursor[d.x], 1);
            int p1 = atomicAdd(&g_cursor[d.y], 1);
            int p2 = atomicAdd(&g_cursor[d.z], 1);
            int p3 = atomicAdd(&g_cursor[d.w], 1);
            g_col_idx[p0] = s.x;
            g_col_idx[p1] = s.y;
            g_col_idx[p2] = s.z;
            g_col_idx[p3] = s.w;
        }
    } else {
        for (int j = i; j < e; j++) {
            int p = atomicAdd(&g_cursor[dst[j]], 1);
            g_col_idx[p] = src[j];
        }
    }
}

__global__ void fill_gemm_kernel(const int* __restrict__ src,
                                 const int* __restrict__ dst, int e,
                                 const float* __restrict__ x,
                                 const float* __restrict__ W, int n,
                                 int gemm_blocks) {
    if ((int)blockIdx.x < gemm_blocks) {
        gemm_body(x, W, n, blockIdx.x);
    } else {
        fill_body(src, dst, e, blockIdx.x - gemm_blocks);
    }
}

// ---------- 6. aggregation (fp16 y, fp32 accum) + right-norm + bias ----------
__global__ void agg_kernel(const float* __restrict__ bias,
                           float* __restrict__ out, int n) {
    int node = (blockIdx.x * blockDim.x + threadIdx.x) >> 5;
    int lane = threadIdx.x & 31;
    if (node >= n) return;

    int beg = g_row_ptr[node];
    int end = g_row_ptr[node + 1];

    const __half* yh = g_yh;
    float4 acc = make_float4(0.f, 0.f, 0.f, 0.f);
    int j = beg;
    while (j + 32 <= end) {
        int idx = g_col_idx[j + lane];
#pragma unroll
        for (int i = 0; i < 32; i++) {
            int s = __shfl_sync(0xffffffffu, idx, i);
            uint2 raw = *(const uint2*)(yh + ((size_t)s << 7) + (lane << 2));
            float2 f0 = __half22float2(*(__half2*)&raw.x);
            float2 f1 = __half22float2(*(__half2*)&raw.y);
            acc.x += f0.x; acc.y += f0.y; acc.z += f1.x; acc.w += f1.y;
        }
        j += 32;
    }
    int rem = end - j;
    if (rem > 0) {
        int idx = (lane < rem) ? g_col_idx[j + lane] : 0;
        for (int i = 0; i < rem; i++) {
            int s = __shfl_sync(0xffffffffu, idx, i);
            uint2 raw = *(const uint2*)(yh + ((size_t)s << 7) + (lane << 2));
            float2 f0 = __half22float2(*(__half2*)&raw.x);
            float2 f1 = __half22float2(*(__half2*)&raw.y);
            acc.x += f0.x; acc.y += f0.y; acc.z += f1.x; acc.w += f1.y;
        }
    }

    float sc = rsqrtf(fmaxf((float)(end - beg), 1.0f));
    float4 b = ((const float4*)bias)[lane];
    float4 o = make_float4(acc.x * sc + b.x, acc.y * sc + b.y,
                           acc.z * sc + b.z, acc.w * sc + b.w);
    *(float4*)(out + ((size_t)node << 7) + (lane << 2)) = o;
}

// ---------- launch ----------
extern "C" void kernel_launch(void* const* d_in, const int* in_sizes, int n_in,
                              void* d_out, int out_size) {
    const float* x    = (const float*)d_in[0];
    const int*   src  = (const int*)d_in[1];
    const int*   dst  = (const int*)d_in[2];
    const float* W    = (const float*)d_in[3];
    const float* bias = (const float*)d_in[4];
    float* out = (float*)d_out;

    int n = in_sizes[0] / F;
    int e = in_sizes[1];
    int e4 = (e + 3) / 4;

    int gemm_blocks = (n + BM - 1) / BM;                           // 391
    int fill_blocks = (e + 256 * FILL_EPT - 1) / (256 * FILL_EPT); // 391

    cudaFuncSetAttribute(fill_gemm_kernel,
                         cudaFuncAttributeMaxDynamicSharedMemorySize,
                         GEMM_SMEM_BYTES);

    zero_kernel<<<(n + 255) / 256, 256>>>(n);
    degree_kernel<<<(e4 + 255) / 256, 256>>>(src, dst, e);
    scan_kernel<<<1, 1024>>>(n);
    fill_gemm_kernel<<<gemm_blocks + fill_blocks, 256, GEMM_SMEM_BYTES>>>(
        src, dst, e, x, W, n, gemm_blocks);
    agg_kernel<<<(n * 32 + 255) / 256, 256>>>(bias, out, n);
}